// round 3
// baseline (speedup 1.0000x reference)
#include <cuda_runtime.h>
#include <cuda_fp16.h>

// Problem constants (fixed by the reference)
#define DVOL   128
#define RES    179
#define NPROJ  10
#define PIX    (RES * RES)          // 32041
#define NPIX   (NPROJ * PIX)        // 320410
#define BW     130                  // padded extent of zi/xi (0..129)
#define BPLANE (BW * BW)            // 16900 entries per k-plane

// 4-corner fp16 table, one uint2 (=4 halves) per entry:
//   C[k][zi][xi] = half4( A[zi-1][xi-1], A[zi-1][xi], A[zi][xi-1], A[zi][xi] )
// where A[z][x] = 0.5*(vol[z][k-1][x] + vol[z][k][x]) (vol[.,-1,.]=0),
// out-of-range z/x (outside [0,127]) contribute 0.
// One LDG.64 at (k, z0+1, x0+1) yields the full bilinear stencil.
__device__ uint2 g_C[DVOL * BPLANE];   // 128*16900*8B ≈ 17.3 MB (L2-resident)

#define STRIP_ROWS 33                  // output zi rows per block (4*33 >= 130)
#define APAD_COLS  132                 // 131 used, padded stride

// Block: (k, strip). Stage the A-plane strip in smem (fp16), then emit the
// 4-corner entries. Grid = 128 k-planes * 4 strips = 512 blocks.
__global__ void __launch_bounds__(256) build_C_kernel(const float* __restrict__ vol) {
    __shared__ __half Apad[(STRIP_ROWS + 1) * APAD_COLS];   // <= 34*132*2B = 9.0KB

    int k = blockIdx.x >> 2;
    int s = blockIdx.x & 3;
    int zi0 = s * STRIP_ROWS;                       // first output zi of this strip
    int nrows_out = min(STRIP_ROWS, BW - zi0);      // <= 33 (31 for last strip)
    int nfill = (nrows_out + 1) * 131;              // Apad rows [0..nrows_out], cols [0..130]

    const float* volk  = vol + k * DVOL;            // vol[(z*128 + k)*128 + x]
    const float* volkm = vol + (k > 0 ? k - 1 : 0) * DVOL;
    bool has_km = (k > 0);

    // Fill Apad[r][c] = A[zi0 + r - 1][c - 1]  (zero outside [0,127]^2)
    for (int e = threadIdx.x; e < nfill; e += 256) {
        int r = e / 131;
        int c = e - r * 131;
        int z = zi0 + r - 1;
        int x = c - 1;
        float a = 0.0f;
        if ((unsigned)z < 128u && (unsigned)x < 128u) {
            float v0 = __ldg(volk  + z * (DVOL * DVOL) + x);
            float v1 = has_km ? __ldg(volkm + z * (DVOL * DVOL) + x) : 0.0f;
            a = 0.5f * (v0 + v1);
        }
        Apad[r * APAD_COLS + c] = __float2half_rn(a);
    }
    __syncthreads();

    // Emit corner entries for zi in [zi0, zi0+nrows_out), xi in [0,130)
    int nout = nrows_out * BW;
    uint2* dst = g_C + k * BPLANE + zi0 * BW;
    for (int e = threadIdx.x; e < nout; e += 256) {
        int r  = e / BW;
        int xi = e - r * BW;
        const __half* row0 = Apad + r * APAD_COLS + xi;
        const __half* row1 = row0 + APAD_COLS;
        __half2 lo = __halves2half2(row0[0], row0[1]);   // (a00, a01)
        __half2 hi = __halves2half2(row1[0], row1[1]);   // (a10, a11)
        uint2 v;
        v.x = *reinterpret_cast<const unsigned int*>(&lo);
        v.y = *reinterpret_cast<const unsigned int*>(&hi);
        dst[e] = v;
    }
}

__global__ void __launch_bounds__(256) project_kernel(
    const float* __restrict__ poses,
    const int*   __restrict__ idx,
    float*       __restrict__ out)
{
    int t = blockIdx.x * blockDim.x + threadIdx.x;
    if (t >= NPIX) return;
    int p   = t / PIX;
    int rem = t - p * PIX;
    int i   = rem / RES;            // detector row  (gx)
    int j   = rem - i * RES;        // detector col  (gy) — contiguous per lane

    int e = __ldg(&idx[p]);
    float ex = __ldg(&poses[e * 3 + 0]);
    float ey = __ldg(&poses[e * 3 + 1]);
    float ez = __ldg(&poses[e * 3 + 2]);

    float gx = (float)i - 89.5f;
    float gy = (float)j - 89.5f;

    // Unnormalized ray; normalization cancels everywhere except dx weight.
    float rx = gx - ex;
    float ry = -ey;                  // detector plane is y = 0
    float rz = gy - ez;
    float n  = sqrtf(rx * rx + ry * ry + rz * rz);
    float inv_ry = 1.0f / ry;
    float dxw = fabsf(inv_ry) * n;

    // Sample position at plane k (volume index space), linear in k:
    //   fz = bz + k*sz   (D axis),   fx = bx + k*sx   (H axis)
    float sz = rx * inv_ry;
    float sx = rz * inv_ry;
    float bz = fmaf(-ey, sz, ex + 63.5f);
    float bx = fmaf(-ey, sx, ez + 63.5f);

    // Trim k to the (conservative) interval where fz,fx are inside [-1.5, 129.5];
    // the exact per-iteration predicate below handles the boundary precisely.
    float lo_k = 0.0f, hi_k = 127.0f;
    {
        if (fabsf(sz) > 1e-12f) {
            float is = 1.0f / sz;
            float t0 = (-1.5f - bz) * is, t1 = (129.5f - bz) * is;
            lo_k = fmaxf(lo_k, fminf(t0, t1));
            hi_k = fminf(hi_k, fmaxf(t0, t1));
        } else if (bz < -1.5f || bz > 129.5f) { lo_k = 1.0f; hi_k = 0.0f; }
        if (fabsf(sx) > 1e-12f) {
            float is = 1.0f / sx;
            float t0 = (-1.5f - bx) * is, t1 = (129.5f - bx) * is;
            lo_k = fmaxf(lo_k, fminf(t0, t1));
            hi_k = fminf(hi_k, fmaxf(t0, t1));
        } else if (bx < -1.5f || bx > 129.5f) { lo_k = 1.0f; hi_k = 0.0f; }
    }
    int kmin = max(0, (int)floorf(lo_k));
    int kmax = min(DVOL - 1, (int)ceilf(hi_k));

    float acc = 0.0f;
    float kf  = (float)kmin;
    int kbase = kmin * BPLANE;
    #pragma unroll 4
    for (int k = kmin; k <= kmax; ++k, kf += 1.0f, kbase += BPLANE) {
        float fz  = fmaf(kf, sz, bz);
        float fx  = fmaf(kf, sx, bx);
        float z0f = floorf(fz);
        float x0f = floorf(fx);
        int zi = (int)z0f + 1;       // 0..129 valid (border rows are zero)
        int xi = (int)x0f + 1;
        if ((unsigned)zi <= 129u && (unsigned)xi <= 129u) {
            float wz = fz - z0f;
            float wx = fx - x0f;
            uint2 raw = __ldg(&g_C[kbase + zi * BW + xi]);
            float2 c01 = __half22float2(*reinterpret_cast<__half2*>(&raw.x));
            float2 c23 = __half22float2(*reinterpret_cast<__half2*>(&raw.y));
            float v0 = fmaf(wx, c01.y - c01.x, c01.x);   // x-lerp, row z0
            float v1 = fmaf(wx, c23.y - c23.x, c23.x);   // x-lerp, row z0+1
            acc += fmaf(wz, v1 - v0, v0);                // z-lerp
        }
    }
    out[t] = acc * dxw;
}

// Tail: reference returns (projections, idx); write idx (as float) after the
// projections if the output buffer has room.
__global__ void write_tail_kernel(const int* __restrict__ idx,
                                  float* __restrict__ out, int tail) {
    int t = threadIdx.x;
    if (t < tail) {
        out[NPIX + t] = (t < NPROJ) ? (float)__ldg(&idx[t]) : 0.0f;
    }
}

extern "C" void kernel_launch(void* const* d_in, const int* in_sizes, int n_in,
                              void* d_out, int out_size) {
    const float* vol   = (const float*)d_in[0];   // I_rec: 1*1*128*128*128 f32
    const float* poses = (const float*)d_in[1];   // 50*3 f32
    const int*   idx   = (const int*)d_in[2];     // 10 i32
    float* out = (float*)d_out;

    build_C_kernel<<<DVOL * 4, 256>>>(vol);
    project_kernel<<<(NPIX + 255) / 256, 256>>>(poses, idx, out);

    if (out_size > NPIX) {
        int tail = out_size - NPIX;
        if (tail > 1024) tail = 1024;
        write_tail_kernel<<<1, 1024>>>(idx, out, tail);
    }
}

// round 4
// speedup vs baseline: 1.1713x; 1.1713x over previous
#include <cuda_runtime.h>

// Problem constants (fixed by the reference)
#define DVOL   128
#define RES    179
#define NPROJ  10
#define PIX    (RES * RES)          // 32041
#define NPIX   (NPROJ * PIX)        // 320410
#define BW2    134                  // padded extent of zi/xi (0..133), z0 = zi-3
#define BPL2   (BW2 * BW2)          // 17956 entries per k-plane
#define ETOT   (DVOL * BPL2)        // 2,298,368 entries

// Bilinear-coefficient table (zero-padded guard band of 3 on each side):
//   E[k][zi][xi] = ( c00, c01-c00, c10-c00, c11-c01-c10+c00 )
// with c_ab = A[z0+a][x0+b], z0 = zi-3, x0 = xi-3,
//      A[z][x] = 0.5*(vol[z][k-1][x] + vol[z][k][x])  (vol[.,-1,.] = 0),
//      A = 0 outside z,x in [0,127].
// sample = e0 + wx*e1 + wz*(e2 + wx*e3)
__device__ float4 g_E[ETOT];        // ~36.8 MB (L2-resident)

__global__ void __launch_bounds__(256) build_E_kernel(const float* __restrict__ vol) {
    int t = blockIdx.x * blockDim.x + threadIdx.x;
    if (t >= ETOT) return;
    int k   = t / BPL2;
    int rem = t - k * BPL2;
    int zi  = rem / BW2;
    int xi  = rem - zi * BW2;
    int z0  = zi - 3;
    int x0  = xi - 3;
    bool hk = (k > 0);
    int km  = hk ? k - 1 : 0;

    float c00 = 0.f, c01 = 0.f, c10 = 0.f, c11 = 0.f;
    {
        int z = z0;
        if ((unsigned)z < 128u) {
            const float* pk = vol + (z * DVOL + k)  * DVOL;
            const float* pm = vol + (z * DVOL + km) * DVOL;
            if ((unsigned)x0       < 128u) c00 = 0.5f * (__ldg(pk + x0)     + (hk ? __ldg(pm + x0)     : 0.f));
            if ((unsigned)(x0 + 1) < 128u) c01 = 0.5f * (__ldg(pk + x0 + 1) + (hk ? __ldg(pm + x0 + 1) : 0.f));
        }
    }
    {
        int z = z0 + 1;
        if ((unsigned)z < 128u) {
            const float* pk = vol + (z * DVOL + k)  * DVOL;
            const float* pm = vol + (z * DVOL + km) * DVOL;
            if ((unsigned)x0       < 128u) c10 = 0.5f * (__ldg(pk + x0)     + (hk ? __ldg(pm + x0)     : 0.f));
            if ((unsigned)(x0 + 1) < 128u) c11 = 0.5f * (__ldg(pk + x0 + 1) + (hk ? __ldg(pm + x0 + 1) : 0.f));
        }
    }
    g_E[t] = make_float4(c00, c01 - c00, c10 - c00, c11 - c01 - c10 + c00);
}

__global__ void __launch_bounds__(256) project_kernel(
    const float* __restrict__ poses,
    const int*   __restrict__ idx,
    float*       __restrict__ out,
    int tail)
{
    int t = blockIdx.x * blockDim.x + threadIdx.x;
    if (t >= NPIX) {
        // fold the idx tail into this launch
        int u = t - NPIX;
        if (u < tail) out[NPIX + u] = (u < NPROJ) ? (float)__ldg(&idx[u]) : 0.0f;
        return;
    }
    int p   = t / PIX;
    int rem = t - p * PIX;
    int i   = rem / RES;            // detector row (gx) — warp-uniform
    int j   = rem - i * RES;        // detector col (gy) — contiguous per lane

    int e = __ldg(&idx[p]);
    float ex = __ldg(&poses[e * 3 + 0]);
    float ey = __ldg(&poses[e * 3 + 1]);
    float ez = __ldg(&poses[e * 3 + 2]);

    float gx = (float)i - 89.5f;
    float gy = (float)j - 89.5f;

    // Unnormalized ray; normalization cancels except in the dx weight.
    float rx = gx - ex;
    float ry = -ey;                  // detector plane is y = 0
    float rz = gy - ez;
    float n  = sqrtf(rx * rx + ry * ry + rz * rz);
    float inv_ry = 1.0f / ry;
    float dxw = fabsf(inv_ry) * n;

    // Sample position at plane k (volume index space), linear in k:
    float sz = rx * inv_ry;
    float sx = rz * inv_ry;
    float bz = fmaf(-ey, sz, ex + 63.5f);
    float bx = fmaf(-ey, sx, ez + 63.5f);

    // Restrictive trim: keep k only where fz,fx in [-2.5, 130.5].
    // Data region is fz in (-1, 129); the extra margin means the guard band
    // (floor in [-3,130] -> zi in [0,133]) makes the inner loop branch-free,
    // and restrictive rounding only drops zero-contribution samples.
    float lo_k = 0.0f, hi_k = 127.0f;
    {
        if (fabsf(sz) > 1e-12f) {
            float is = 1.0f / sz;
            float t0 = (-2.5f - bz) * is, t1 = (130.5f - bz) * is;
            lo_k = fmaxf(lo_k, fminf(t0, t1));
            hi_k = fminf(hi_k, fmaxf(t0, t1));
        } else if (bz < -2.5f || bz > 130.5f) { lo_k = 1.0f; hi_k = 0.0f; }
        if (fabsf(sx) > 1e-12f) {
            float is = 1.0f / sx;
            float t0 = (-2.5f - bx) * is, t1 = (130.5f - bx) * is;
            lo_k = fmaxf(lo_k, fminf(t0, t1));
            hi_k = fminf(hi_k, fmaxf(t0, t1));
        } else if (bx < -2.5f || bx > 130.5f) { lo_k = 1.0f; hi_k = 0.0f; }
    }
    int kmin = max(0, (int)ceilf(lo_k));
    int kmax = min(DVOL - 1, (int)floorf(hi_k));

    float accA = 0.0f, accB = 0.0f;
    const float4* __restrict__ tp = g_E + (size_t)kmin * BPL2;
    float kf = (float)kmin;
    #pragma unroll 4
    for (int k = kmin; k <= kmax; ++k, kf += 1.0f, tp += BPL2) {
        float fz = fmaf(kf, sz, bz);
        float fx = fmaf(kf, sx, bx);
        float zf = floorf(fz);
        float xf = floorf(fx);
        float wz = fz - zf;
        float wx = fx - xf;
        int zi = (int)zf + 3;        // 0..133, guard entries are zero
        int xi = (int)xf + 3;
        float4 c = __ldg(tp + zi * BW2 + xi);
        float t0 = fmaf(wx, c.y, c.x);
        float t1 = fmaf(wx, c.w, c.z);
        accA += t0;                        // independent chains
        accB  = fmaf(wz, t1, accB);
    }
    out[t] = (accA + accB) * dxw;
}

extern "C" void kernel_launch(void* const* d_in, const int* in_sizes, int n_in,
                              void* d_out, int out_size) {
    const float* vol   = (const float*)d_in[0];   // I_rec: 1*1*128*128*128 f32
    const float* poses = (const float*)d_in[1];   // 50*3 f32
    const int*   idx   = (const int*)d_in[2];     // 10 i32
    float* out = (float*)d_out;

    build_E_kernel<<<(ETOT + 255) / 256, 256>>>(vol);

    int tail = out_size - NPIX;
    if (tail < 0) tail = 0;
    if (tail > 1024) tail = 1024;
    int total_threads = NPIX + tail;
    project_kernel<<<(total_threads + 255) / 256, 256>>>(poses, idx, out, tail);
}